// round 8
// baseline (speedup 1.0000x reference)
#include <cuda_runtime.h>
#include <cuda_bf16.h>
#include <limits.h>

// Sorted-segment-sum of gathered values:
//   out[s] = sum over j with seg[j]==s of cv[idx[j]]
// seg[] sorted ascending. Empty segments must be 0 (out is poisoned).
//
// Each warp handles ONE 512-edge chunk (16 edges/thread via 4x int4 loads,
// 16 gathers in flight per thread -> deep MLP). Streaming loads use __ldcs
// (evict-first); gathers use __ldcg (L2-only: table >> per-SM L1).
// Per-thread run detection; interior runs flush directly; trailing runs
// combined by a ballot-based clamped warp scan. PDL overlaps the zero-init
// kernel with the load prologue.

#define FULL 0xffffffffu
#define CHUNK 512          // edges per warp (16 per thread)
#define WARPS_PER_BLK 8

__global__ void zero_out_kernel(float4* __restrict__ out4, int n4,
                                float* __restrict__ out, int n) {
    int i = blockIdx.x * blockDim.x + threadIdx.x;
    if (i < n4) out4[i] = make_float4(0.f, 0.f, 0.f, 0.f);
    int r = n4 * 4 + i;
    if (i < (n - n4 * 4)) out[r] = 0.0f;
#if __CUDA_ARCH__ >= 900
    cudaTriggerProgrammaticLaunchCompletion();
#endif
}

__global__ __launch_bounds__(256)
void seg_sum_kernel(const float* __restrict__ cv,
                    const int*   __restrict__ idx,
                    const int*   __restrict__ seg,
                    float*       __restrict__ out,
                    int E)
{
    const int lane = threadIdx.x & 31;
    const long long w =
        (long long)blockIdx.x * WARPS_PER_BLK + (threadIdx.x >> 5);

    long long base = w * (long long)CHUNK;
    if (base >= (long long)E) {
#if __CUDA_ARCH__ >= 900
        cudaGridDependencySynchronize();
#endif
        return;
    }

    if (base + CHUNK <= (long long)E) {
        // ---------------- fast path: one full 512-edge chunk ----------------
        const int4* idx4 = (const int4*)idx;
        const int4* seg4 = (const int4*)seg;

        long long q = (base >> 2) + lane * 4;   // 4 consecutive int4 = 16 edges

        int4 sv4[4], iv4[4];
        #pragma unroll
        for (int k = 0; k < 4; k++) sv4[k] = __ldcs(&seg4[q + k]);
        #pragma unroll
        for (int k = 0; k < 4; k++) iv4[k] = __ldcs(&idx4[q + k]);

        float v_arr[16];
        #pragma unroll
        for (int k = 0; k < 4; k++) {
            v_arr[4 * k + 0] = __ldcg(&cv[iv4[k].x]);
            v_arr[4 * k + 1] = __ldcg(&cv[iv4[k].y]);
            v_arr[4 * k + 2] = __ldcg(&cv[iv4[k].z]);
            v_arr[4 * k + 3] = __ldcg(&cv[iv4[k].w]);
        }

        int s_arr[16];
        #pragma unroll
        for (int k = 0; k < 4; k++) {
            s_arr[4 * k + 0] = sv4[k].x;
            s_arr[4 * k + 1] = sv4[k].y;
            s_arr[4 * k + 2] = sv4[k].z;
            s_arr[4 * k + 3] = sv4[k].w;
        }

#if __CUDA_ARCH__ >= 900
        // output writes below depend on the zero-init kernel
        cudaGridDependencySynchronize();
#endif

        // per-thread run detection over 16 consecutive edges
        float run = v_arr[0];
        int   rs  = s_arr[0];
        const int sfirst = s_arr[0];
        float lead = 0.0f;
        bool  leadDone = false;
        #pragma unroll
        for (int i = 1; i < 16; i++) {
            if (s_arr[i] == rs) {
                run += v_arr[i];
            } else {
                if (!leadDone) { lead = run; leadDone = true; }
                else           { atomicAdd(&out[rs], run); }  // interior: complete
                run = v_arr[i];
                rs  = s_arr[i];
            }
        }
        const float trail   = run;     // if allsame: total of all 16
        const int   slast   = rs;
        const bool  allsame = !leadDone;

        // connectivity with the preceding lane
        int  prev_slast = __shfl_up_sync(FULL, slast, 1);
        bool connected  = (lane != 0) && (prev_slast == sfirst);

        float sv = trail;
        bool  f  = (lane == 0) || !allsame || !connected;  // chain break

        // ballot-based clamped inclusive scan over trailing-run chain
        unsigned head_mask = __ballot_sync(FULL, f);       // bit0 always set
        unsigned mask_le   = head_mask & (FULL >> (31 - lane));
        int seg_start = 31 - __clz(mask_le);
        #pragma unroll
        for (int d = 1; d < 32; d <<= 1) {
            float y = __shfl_up_sync(FULL, sv, d);
            if (lane - d >= seg_start) sv += y;
        }

        // chain-sum ending at lane-1 (completed prefix for segment sfirst)
        float inc_prev = __shfl_up_sync(FULL, sv, 1);

        // flush this thread's leading run (complete since !allsame)
        if (!allsame) {
            float add = lead + (connected ? inc_prev : 0.0f);
            atomicAdd(&out[sfirst], add);
        }

        // trailing-run flush: complete if the next lane doesn't continue it
        int  next_sfirst    = __shfl_down_sync(FULL, sfirst, 1);
        bool next_connected = (lane < 31) && (next_sfirst == slast);
        if (!next_connected) {
            atomicAdd(&out[slast], sv);   // lane 31 always flushes its chain
        }
    } else {
        // ---------------- scalar tail path (last partial chunk) ----------------
#if __CUDA_ARCH__ >= 900
        cudaGridDependencySynchronize();
#endif
        long long lim = (long long)E;
        float carry     = 0.0f;
        int   carry_seg = -1;

        for (long long p = base; p < lim; p += 32) {
            long long j = p + lane;
            bool valid  = (j < lim);

            int   s = INT_MAX;
            float v = 0.0f;
            if (valid) {
                s = seg[j];
                v = __ldg(&cv[idx[j]]);
            }

            int  s_prev = __shfl_up_sync(FULL, s, 1);
            bool head   = (lane == 0) || (s != s_prev);
            unsigned head_mask = __ballot_sync(FULL, head);

            unsigned mask_le = head_mask & (FULL >> (31 - lane));
            int seg_start = 31 - __clz(mask_le);

            float x = v;
            #pragma unroll
            for (int d = 1; d < 32; d <<= 1) {
                float y = __shfl_up_sync(FULL, x, d);
                if (lane - d >= seg_start) x += y;
            }

            int s0 = __shfl_sync(FULL, s, 0);
            if (carry_seg == s0) {
                if (seg_start == 0) x += carry;
            } else if (carry_seg >= 0) {
                if (lane == 0) atomicAdd(&out[carry_seg], carry);
            }

            bool tail = (lane == 31) || ((head_mask >> (lane + 1)) & 1u);
            if (tail && lane != 31 && valid) {
                atomicAdd(&out[s], x);
            }

            carry   = __shfl_sync(FULL, x, 31);
            int s31 = __shfl_sync(FULL, s, 31);
            carry_seg = (s31 == INT_MAX) ? -1 : s31;
        }

        if (carry_seg >= 0 && lane == 0) {
            atomicAdd(&out[carry_seg], carry);
        }
    }
}

extern "C" void kernel_launch(void* const* d_in, const int* in_sizes, int n_in,
                              void* d_out, int out_size)
{
    const float* cv  = (const float*)d_in[0];
    const int*   idx = (const int*)d_in[1];
    const int*   seg = (const int*)d_in[2];
    float*       out = (float*)d_out;

    const int E = in_sizes[1];
    const int N = out_size;

    // 1) zero-init output (poisoned; empty segments must be 0)
    {
        int n4 = N / 4;
        int threads = 256;
        int blocks  = (n4 + threads - 1) / threads;
        if (blocks < 1) blocks = 1;
        zero_out_kernel<<<blocks, threads>>>((float4*)out, n4, out, N);
    }

    // 2) segmented sum, PDL-overlapped with the zero kernel's tail
    {
        long long n_warps  = ((long long)E + CHUNK - 1) / CHUNK;
        long long n_blocks = (n_warps + WARPS_PER_BLK - 1) / WARPS_PER_BLK;

        cudaLaunchConfig_t cfg = {};
        cfg.gridDim  = dim3((unsigned)n_blocks, 1, 1);
        cfg.blockDim = dim3(256, 1, 1);
        cfg.dynamicSmemBytes = 0;
        cfg.stream = 0;
        cudaLaunchAttribute attrs[1];
        attrs[0].id = cudaLaunchAttributeProgrammaticStreamSerialization;
        attrs[0].val.programmaticStreamSerializationAllowed = 1;
        cfg.attrs = attrs;
        cfg.numAttrs = 1;

        cudaError_t rc = cudaLaunchKernelEx(&cfg, seg_sum_kernel,
                                            cv, idx, seg, out, E);
        if (rc != cudaSuccess) {
            // fallback: plain serialized launch (device-side sync is a no-op)
            seg_sum_kernel<<<(int)n_blocks, 256>>>(cv, idx, seg, out, E);
        }
    }
}

// round 9
// speedup vs baseline: 1.0275x; 1.0275x over previous
#include <cuda_runtime.h>
#include <cuda_bf16.h>
#include <limits.h>

// Sorted-segment-sum of gathered values:
//   out[s] = sum over j with seg[j]==s of cv[idx[j]]
// seg[] sorted ascending. Empty segments must be 0 (out is poisoned).
//
// Each warp handles ONE 256-edge chunk (8 edges/thread via 2x int4 loads).
// idx loads issue first (gathers depend on them); seg loads overlap gather
// latency. Streaming loads use __ldcs (evict-first) to preserve L1 for the
// gathered child table. Per-thread run detection; interior runs flush
// directly; trailing runs combined by a ballot-based clamped warp scan.
// PDL overlaps the zero-init kernel with the load prologue.

#define FULL 0xffffffffu
#define CHUNK 256          // edges per warp (8 per thread)
#define WARPS_PER_BLK 8

__global__ void zero_out_kernel(float4* __restrict__ out4, int n4,
                                float* __restrict__ out, int n) {
    int i = blockIdx.x * blockDim.x + threadIdx.x;
    if (i < n4) out4[i] = make_float4(0.f, 0.f, 0.f, 0.f);
    int r = n4 * 4 + i;
    if (i < (n - n4 * 4)) out[r] = 0.0f;
#if __CUDA_ARCH__ >= 900
    cudaTriggerProgrammaticLaunchCompletion();
#endif
}

__global__ __launch_bounds__(256, 8)
void seg_sum_kernel(const float* __restrict__ cv,
                    const int*   __restrict__ idx,
                    const int*   __restrict__ seg,
                    float*       __restrict__ out,
                    int E)
{
    const int lane = threadIdx.x & 31;
    const long long w =
        (long long)blockIdx.x * WARPS_PER_BLK + (threadIdx.x >> 5);

    long long base = w * (long long)CHUNK;
    if (base >= (long long)E) {
#if __CUDA_ARCH__ >= 900
        cudaGridDependencySynchronize();
#endif
        return;
    }

    if (base + CHUNK <= (long long)E) {
        // ---------------- fast path: one full 256-edge chunk ----------------
        const int4* idx4 = (const int4*)idx;
        const int4* seg4 = (const int4*)seg;

        long long q = (base >> 2) + lane * 2;   // 2 consecutive int4 = 8 edges

        // idx first: gathers depend on these
        int4 ia = __ldcs(&idx4[q]);
        int4 ib = __ldcs(&idx4[q + 1]);

        float v_arr[8];
        v_arr[0] = __ldg(&cv[ia.x]);
        v_arr[1] = __ldg(&cv[ia.y]);
        v_arr[2] = __ldg(&cv[ia.z]);
        v_arr[3] = __ldg(&cv[ia.w]);

        int4 sa = __ldcs(&seg4[q]);       // overlap gather latency
        int4 sb = __ldcs(&seg4[q + 1]);

        v_arr[4] = __ldg(&cv[ib.x]);
        v_arr[5] = __ldg(&cv[ib.y]);
        v_arr[6] = __ldg(&cv[ib.z]);
        v_arr[7] = __ldg(&cv[ib.w]);

        int s_arr[8] = { sa.x, sa.y, sa.z, sa.w, sb.x, sb.y, sb.z, sb.w };

#if __CUDA_ARCH__ >= 900
        // output writes below depend on the zero-init kernel
        cudaGridDependencySynchronize();
#endif

        // per-thread run detection over 8 consecutive edges
        float run = v_arr[0];
        int   rs  = s_arr[0];
        const int sfirst = s_arr[0];
        float lead = 0.0f;
        bool  leadDone = false;
        #pragma unroll
        for (int i = 1; i < 8; i++) {
            if (s_arr[i] == rs) {
                run += v_arr[i];
            } else {
                if (!leadDone) { lead = run; leadDone = true; }
                else           { atomicAdd(&out[rs], run); }  // interior: complete
                run = v_arr[i];
                rs  = s_arr[i];
            }
        }
        const float trail   = run;     // if allsame: total of all 8
        const int   slast   = rs;
        const bool  allsame = !leadDone;

        // connectivity with the preceding lane
        int  prev_slast = __shfl_up_sync(FULL, slast, 1);
        bool connected  = (lane != 0) && (prev_slast == sfirst);

        float sv = trail;
        bool  f  = (lane == 0) || !allsame || !connected;  // chain break

        // ballot-based clamped inclusive scan over trailing-run chain
        unsigned head_mask = __ballot_sync(FULL, f);       // bit0 always set
        unsigned mask_le   = head_mask & (FULL >> (31 - lane));
        int seg_start = 31 - __clz(mask_le);
        #pragma unroll
        for (int d = 1; d < 32; d <<= 1) {
            float y = __shfl_up_sync(FULL, sv, d);
            if (lane - d >= seg_start) sv += y;
        }

        // chain-sum ending at lane-1 (completed prefix for segment sfirst)
        float inc_prev = __shfl_up_sync(FULL, sv, 1);

        // flush this thread's leading run (complete since !allsame)
        if (!allsame) {
            float add = lead + (connected ? inc_prev : 0.0f);
            atomicAdd(&out[sfirst], add);
        }

        // trailing-run flush: complete if the next lane doesn't continue it
        int  next_sfirst    = __shfl_down_sync(FULL, sfirst, 1);
        bool next_connected = (lane < 31) && (next_sfirst == slast);
        if (!next_connected) {
            atomicAdd(&out[slast], sv);   // lane 31 always flushes its chain
        }
    } else {
        // ---------------- scalar tail path (last partial chunk) ----------------
#if __CUDA_ARCH__ >= 900
        cudaGridDependencySynchronize();
#endif
        long long lim = (long long)E;
        float carry     = 0.0f;
        int   carry_seg = -1;

        for (long long p = base; p < lim; p += 32) {
            long long j = p + lane;
            bool valid  = (j < lim);

            int   s = INT_MAX;
            float v = 0.0f;
            if (valid) {
                s = seg[j];
                v = __ldg(&cv[idx[j]]);
            }

            int  s_prev = __shfl_up_sync(FULL, s, 1);
            bool head   = (lane == 0) || (s != s_prev);
            unsigned head_mask = __ballot_sync(FULL, head);

            unsigned mask_le = head_mask & (FULL >> (31 - lane));
            int seg_start = 31 - __clz(mask_le);

            float x = v;
            #pragma unroll
            for (int d = 1; d < 32; d <<= 1) {
                float y = __shfl_up_sync(FULL, x, d);
                if (lane - d >= seg_start) x += y;
            }

            int s0 = __shfl_sync(FULL, s, 0);
            if (carry_seg == s0) {
                if (seg_start == 0) x += carry;
            } else if (carry_seg >= 0) {
                if (lane == 0) atomicAdd(&out[carry_seg], carry);
            }

            bool tail = (lane == 31) || ((head_mask >> (lane + 1)) & 1u);
            if (tail && lane != 31 && valid) {
                atomicAdd(&out[s], x);
            }

            carry   = __shfl_sync(FULL, x, 31);
            int s31 = __shfl_sync(FULL, s, 31);
            carry_seg = (s31 == INT_MAX) ? -1 : s31;
        }

        if (carry_seg >= 0 && lane == 0) {
            atomicAdd(&out[carry_seg], carry);
        }
    }
}

extern "C" void kernel_launch(void* const* d_in, const int* in_sizes, int n_in,
                              void* d_out, int out_size)
{
    const float* cv  = (const float*)d_in[0];
    const int*   idx = (const int*)d_in[1];
    const int*   seg = (const int*)d_in[2];
    float*       out = (float*)d_out;

    const int E = in_sizes[1];
    const int N = out_size;

    // prefer maximum L1D (no shared memory used)
    static bool carveout_set = false;
    if (!carveout_set) {
        cudaFuncSetAttribute(seg_sum_kernel,
                             cudaFuncAttributePreferredSharedMemoryCarveout, 0);
        carveout_set = true;
    }

    // 1) zero-init output (poisoned; empty segments must be 0)
    {
        int n4 = N / 4;
        int threads = 256;
        int blocks  = (n4 + threads - 1) / threads;
        if (blocks < 1) blocks = 1;
        zero_out_kernel<<<blocks, threads>>>((float4*)out, n4, out, N);
    }

    // 2) segmented sum, PDL-overlapped with the zero kernel's tail
    {
        long long n_warps  = ((long long)E + CHUNK - 1) / CHUNK;
        long long n_blocks = (n_warps + WARPS_PER_BLK - 1) / WARPS_PER_BLK;

        cudaLaunchConfig_t cfg = {};
        cfg.gridDim  = dim3((unsigned)n_blocks, 1, 1);
        cfg.blockDim = dim3(256, 1, 1);
        cfg.dynamicSmemBytes = 0;
        cfg.stream = 0;
        cudaLaunchAttribute attrs[1];
        attrs[0].id = cudaLaunchAttributeProgrammaticStreamSerialization;
        attrs[0].val.programmaticStreamSerializationAllowed = 1;
        cfg.attrs = attrs;
        cfg.numAttrs = 1;

        cudaError_t rc = cudaLaunchKernelEx(&cfg, seg_sum_kernel,
                                            cv, idx, seg, out, E);
        if (rc != cudaSuccess) {
            // fallback: plain serialized launch (device-side sync is a no-op)
            seg_sum_kernel<<<(int)n_blocks, 256>>>(cv, idx, seg, out, E);
        }
    }
}